// round 1
// baseline (speedup 1.0000x reference)
#include <cuda_runtime.h>

#define NN 100000
#define NE 600000
#define DD 128
#define NLAYER 5
#define TILE 64
#define ZPITCH 132   // 128 + 4 pad: keeps 16B alignment, breaks LDS bank collisions

// Scratch (static __device__ arrays — no allocation allowed)
__device__ float g_hA[NN * DD];
__device__ float g_hB[NN * DD];
__device__ int   g_deg[NN];
__device__ int   g_rowstart[NN + 1];
__device__ int   g_cursor[NN];
__device__ int   g_csr[NE];
__device__ int   g_bsum[128];
__device__ int   g_boff[128];
__device__ float g_pp[256 * DD];

// ---------------------------------------------------------------- CSR build
__global__ void k_zero() {
    int i = blockIdx.x * blockDim.x + threadIdx.x;
    if (i < NN) g_deg[i] = 0;
}

__global__ void k_count(const int* __restrict__ dst) {
    int e = blockIdx.x * blockDim.x + threadIdx.x;
    if (e < NE) atomicAdd(&g_deg[dst[e]], 1);
}

__global__ void k_scan_block() {  // grid = ceil(NN/1024), block = 1024
    __shared__ int s[1024];
    int tid = threadIdx.x;
    int i = blockIdx.x * 1024 + tid;
    int v = (i < NN) ? g_deg[i] : 0;
    s[tid] = v;
    __syncthreads();
    for (int off = 1; off < 1024; off <<= 1) {
        int t = (tid >= off) ? s[tid - off] : 0;
        __syncthreads();
        s[tid] += t;
        __syncthreads();
    }
    if (i < NN) g_rowstart[i] = s[tid] - v;          // exclusive within block
    if (tid == 1023) g_bsum[blockIdx.x] = s[1023];   // block total
}

__global__ void k_scan_top() {   // 1 block, 128 threads (98 block sums)
    __shared__ int s[128];
    int tid = threadIdx.x;
    int v = (tid < (NN + 1023) / 1024) ? g_bsum[tid] : 0;
    s[tid] = v;
    __syncthreads();
    for (int off = 1; off < 128; off <<= 1) {
        int t = (tid >= off) ? s[tid - off] : 0;
        __syncthreads();
        s[tid] += t;
        __syncthreads();
    }
    g_boff[tid] = s[tid] - v;
}

__global__ void k_scan_add() {
    int i = blockIdx.x * blockDim.x + threadIdx.x;
    if (i < NN) {
        int r = g_rowstart[i] + g_boff[i >> 10];
        g_rowstart[i] = r;
        g_cursor[i]   = r;
    }
    if (i == 0) g_rowstart[NN] = NE;
}

__global__ void k_scatter(const int* __restrict__ src, const int* __restrict__ dst) {
    int e = blockIdx.x * blockDim.x + threadIdx.x;
    if (e < NE) {
        int p = atomicAdd(&g_cursor[dst[e]], 1);
        g_csr[p] = src[e];
    }
}

// ---------------------------------------------------------------- embedding gather
__global__ void k_gather(const int* __restrict__ x, const float* __restrict__ emb) {
    int idx = blockIdx.x * blockDim.x + threadIdx.x;
    if (idx < NN * 32) {
        int node = idx >> 5, q = idx & 31;
        ((float4*)g_hA)[(size_t)node * 32 + q] =
            ((const float4*)emb)[(size_t)x[node] * 32 + q];
    }
}

// ---------------------------------------------------------------- fused GIN layer
// block = 256 threads, tile = 64 nodes. SMEM: W(16384f) + z(64*132f) + t(64*132f)
__global__ void __launch_bounds__(256, 1) k_layer(
    const float* __restrict__ h_in, float* __restrict__ h_out,
    const float* __restrict__ Wa, const float* __restrict__ ba,
    const float* __restrict__ Wb, const float* __restrict__ bb)
{
    extern __shared__ float smem[];
    float* W_s = smem;                     // 128*128
    float* z_s = smem + DD * DD;           // 64*132
    float* t_s = z_s + TILE * ZPITCH;      // 64*132

    const int tid  = threadIdx.x;
    const int lane = tid & 31;
    const int warp = tid >> 5;
    const int tileBase = blockIdx.x * TILE;

    // ---- Phase 0: aggregation  z = h + sum_{j->i} h[src_j]
    for (int i = 0; i < 8; i++) {
        int ln = warp * 8 + i;
        int gn = tileBase + ln;
        float4 acc = make_float4(0.f, 0.f, 0.f, 0.f);
        if (gn < NN) {
            acc = ((const float4*)(h_in + (size_t)gn * DD))[lane];
            int j   = g_rowstart[gn];
            int end = g_rowstart[gn + 1];
            for (; j + 4 <= end; j += 4) {
                int s0 = g_csr[j], s1 = g_csr[j + 1], s2 = g_csr[j + 2], s3 = g_csr[j + 3];
                float4 v0 = ((const float4*)(h_in + (size_t)s0 * DD))[lane];
                float4 v1 = ((const float4*)(h_in + (size_t)s1 * DD))[lane];
                float4 v2 = ((const float4*)(h_in + (size_t)s2 * DD))[lane];
                float4 v3 = ((const float4*)(h_in + (size_t)s3 * DD))[lane];
                acc.x += (v0.x + v1.x) + (v2.x + v3.x);
                acc.y += (v0.y + v1.y) + (v2.y + v3.y);
                acc.z += (v0.z + v1.z) + (v2.z + v3.z);
                acc.w += (v0.w + v1.w) + (v2.w + v3.w);
            }
            for (; j < end; j++) {
                int s0 = g_csr[j];
                float4 v0 = ((const float4*)(h_in + (size_t)s0 * DD))[lane];
                acc.x += v0.x; acc.y += v0.y; acc.z += v0.z; acc.w += v0.w;
            }
        }
        ((float4*)(z_s + ln * ZPITCH))[lane] = acc;
    }

    // ---- load Wa into SMEM
    {
        const float4* Wg = (const float4*)Wa;
        float4* W4 = (float4*)W_s;
        for (int idx = tid; idx < DD * DD / 4; idx += 256) W4[idx] = Wg[idx];
    }
    __syncthreads();

    const int tx = tid & 15;
    const int ty = tid >> 4;
    const int r0 = ty * 4;
    const int c0 = tx * 8;

    // ---- GEMM1: t = relu(z @ Wa + ba)
    float acc[4][8];
    #pragma unroll
    for (int i = 0; i < 4; i++)
        #pragma unroll
        for (int j = 0; j < 8; j++) acc[i][j] = 0.f;

    {
        const float4* W4 = (const float4*)W_s;
        #pragma unroll 4
        for (int k = 0; k < DD; k++) {
            float a[4];
            #pragma unroll
            for (int i = 0; i < 4; i++) a[i] = z_s[(r0 + i) * ZPITCH + k];
            float4 b0 = W4[k * (DD / 4) + tx * 2];
            float4 b1 = W4[k * (DD / 4) + tx * 2 + 1];
            float b[8] = {b0.x, b0.y, b0.z, b0.w, b1.x, b1.y, b1.z, b1.w};
            #pragma unroll
            for (int i = 0; i < 4; i++)
                #pragma unroll
                for (int j = 0; j < 8; j++) acc[i][j] += a[i] * b[j];
        }
    }

    {
        float bav[8];
        #pragma unroll
        for (int j = 0; j < 8; j++) bav[j] = ba[c0 + j];
        #pragma unroll
        for (int i = 0; i < 4; i++) {
            float4 p0, p1;
            p0.x = fmaxf(acc[i][0] + bav[0], 0.f);
            p0.y = fmaxf(acc[i][1] + bav[1], 0.f);
            p0.z = fmaxf(acc[i][2] + bav[2], 0.f);
            p0.w = fmaxf(acc[i][3] + bav[3], 0.f);
            p1.x = fmaxf(acc[i][4] + bav[4], 0.f);
            p1.y = fmaxf(acc[i][5] + bav[5], 0.f);
            p1.z = fmaxf(acc[i][6] + bav[6], 0.f);
            p1.w = fmaxf(acc[i][7] + bav[7], 0.f);
            float* row = t_s + (r0 + i) * ZPITCH + c0;
            ((float4*)row)[0] = p0;
            ((float4*)(row + 4))[0] = p1;
        }
    }
    __syncthreads();

    // ---- load Wb into SMEM (reuse W_s)
    {
        const float4* Wg = (const float4*)Wb;
        float4* W4 = (float4*)W_s;
        for (int idx = tid; idx < DD * DD / 4; idx += 256) W4[idx] = Wg[idx];
    }
    __syncthreads();

    // ---- GEMM2: h' = relu(t @ Wb + bb)
    #pragma unroll
    for (int i = 0; i < 4; i++)
        #pragma unroll
        for (int j = 0; j < 8; j++) acc[i][j] = 0.f;

    {
        const float4* W4 = (const float4*)W_s;
        #pragma unroll 4
        for (int k = 0; k < DD; k++) {
            float a[4];
            #pragma unroll
            for (int i = 0; i < 4; i++) a[i] = t_s[(r0 + i) * ZPITCH + k];
            float4 b0 = W4[k * (DD / 4) + tx * 2];
            float4 b1 = W4[k * (DD / 4) + tx * 2 + 1];
            float b[8] = {b0.x, b0.y, b0.z, b0.w, b1.x, b1.y, b1.z, b1.w};
            #pragma unroll
            for (int i = 0; i < 4; i++)
                #pragma unroll
                for (int j = 0; j < 8; j++) acc[i][j] += a[i] * b[j];
        }
    }

    {
        float bbv[8];
        #pragma unroll
        for (int j = 0; j < 8; j++) bbv[j] = bb[c0 + j];
        #pragma unroll
        for (int i = 0; i < 4; i++) {
            int gn = tileBase + r0 + i;
            if (gn < NN) {
                float4 p0, p1;
                p0.x = fmaxf(acc[i][0] + bbv[0], 0.f);
                p0.y = fmaxf(acc[i][1] + bbv[1], 0.f);
                p0.z = fmaxf(acc[i][2] + bbv[2], 0.f);
                p0.w = fmaxf(acc[i][3] + bbv[3], 0.f);
                p1.x = fmaxf(acc[i][4] + bbv[4], 0.f);
                p1.y = fmaxf(acc[i][5] + bbv[5], 0.f);
                p1.z = fmaxf(acc[i][6] + bbv[6], 0.f);
                p1.w = fmaxf(acc[i][7] + bbv[7], 0.f);
                float* row = h_out + (size_t)gn * DD + c0;
                ((float4*)row)[0] = p0;
                ((float4*)(row + 4))[0] = p1;
            }
        }
    }
}

// ---------------------------------------------------------------- pooling + head
__global__ void k_pool(const float* __restrict__ h) {  // grid=256, block=128
    int c = threadIdx.x;
    float acc = 0.f;
    for (int i = blockIdx.x; i < NN; i += gridDim.x)
        acc += h[(size_t)i * DD + c];
    g_pp[blockIdx.x * DD + c] = acc;   // deterministic partials, no float atomics
}

__global__ void k_final(const float* __restrict__ Wlin,
                        const float* __restrict__ blin,
                        float* __restrict__ out) {  // 1 block, 128 threads
    __shared__ float p[DD];
    int c = threadIdx.x;
    float acc = 0.f;
    for (int b = 0; b < 256; b++) acc += g_pp[b * DD + c];
    p[c] = acc;
    __syncthreads();
    float o = blin[c];
    #pragma unroll 8
    for (int k = 0; k < DD; k++) o += p[k] * Wlin[k * DD + c];
    out[c] = o;
}

// ---------------------------------------------------------------- launch
extern "C" void kernel_launch(void* const* d_in, const int* in_sizes, int n_in,
                              void* d_out, int out_size) {
    const int*   x    = (const int*)d_in[0];
    const int*   ei   = (const int*)d_in[1];
    const float* emb  = (const float*)d_in[2];
    const float* Wa   = (const float*)d_in[3];
    const float* ba   = (const float*)d_in[4];
    const float* Wb   = (const float*)d_in[5];
    const float* bb   = (const float*)d_in[6];
    const float* Wlin = (const float*)d_in[7];
    const float* blin = (const float*)d_in[8];
    float* out = (float*)d_out;

    const int* src = ei;
    const int* dst = ei + NE;

    const size_t smem = (size_t)(DD * DD + 2 * TILE * ZPITCH) * sizeof(float);
    cudaFuncSetAttribute(k_layer, cudaFuncAttributeMaxDynamicSharedMemorySize, (int)smem);

    // CSR build
    k_zero<<<(NN + 255) / 256, 256>>>();
    k_count<<<(NE + 255) / 256, 256>>>(dst);
    k_scan_block<<<(NN + 1023) / 1024, 1024>>>();
    k_scan_top<<<1, 128>>>();
    k_scan_add<<<(NN + 255) / 256, 256>>>();
    k_scatter<<<(NE + 255) / 256, 256>>>(src, dst);

    // embedding gather
    k_gather<<<(NN * 32 + 255) / 256, 256>>>(x, emb);

    // layers (ping-pong)
    void *pA, *pB;
    cudaGetSymbolAddress(&pA, g_hA);
    cudaGetSymbolAddress(&pB, g_hB);
    float* hbuf[2] = {(float*)pA, (float*)pB};
    int cur = 0;
    const int grid = (NN + TILE - 1) / TILE;
    for (int l = 0; l < NLAYER; l++) {
        k_layer<<<grid, 256, smem>>>(hbuf[cur], hbuf[1 - cur],
                                     Wa + (size_t)l * DD * DD, ba + (size_t)l * DD,
                                     Wb + (size_t)l * DD * DD, bb + (size_t)l * DD);
        cur ^= 1;
    }

    // pool + head
    k_pool<<<256, 128>>>(hbuf[cur]);
    k_final<<<1, 128>>>(Wlin, blin, out);
}

// round 6
// speedup vs baseline: 1.8249x; 1.8249x over previous
#include <cuda_runtime.h>
#include <cuda_bf16.h>
#include <cstdint>

#define NN 100000
#define NE 600000
#define DD 128
#define NLAYER 5
#define TILE_M 128
#define NBLK ((NN + TILE_M - 1) / TILE_M)

#define PITCH 272                       // bytes per 128-bf16 row (256 + 16 pad)
#define IMG   (128 * PITCH)             // 34816 bytes per image
#define WBYTES (4 * IMG)                // WaH|WaL|WbH|WbL per layer = 139264

// SMEM layout (bytes)
#define SM_MBAR 0
#define SM_BA   16
#define SM_BB   528
#define SM_A    1088                    // A_hi image
#define SM_AL   (SM_A + IMG)            // A_lo image
#define SM_B    (SM_AL + IMG)           // 4 weight images
#define SM_TOTAL (SM_B + 4 * IMG)       // 209984

// ---------------- scratch ----------------
__device__ __align__(128) float g_hA[NN * DD];
__device__ __align__(128) float g_hB[NN * DD];
__device__ int   g_deg[NN];
__device__ int   g_rowstart[NN + 1];
__device__ int   g_cursor[NN];
__device__ int   g_csr[NE];
__device__ int   g_bsum[128];
__device__ int   g_boff[128];
__device__ float g_pp[256 * DD];
__device__ __align__(128) unsigned char g_Wt[NLAYER * 4 * IMG];  // [n][k] bf16 hi/lo images

// ---------------- helpers ----------------
__device__ __forceinline__ uint32_t smem_u32(const void* p) {
    uint32_t a;
    asm("{ .reg .u64 t; cvta.to.shared.u64 t, %1; cvt.u32.u64 %0, t; }" : "=r"(a) : "l"(p));
    return a;
}
#define MBAR_INIT(a, c) asm volatile("mbarrier.init.shared.b64 [%0], %1;" :: "r"(a), "r"(c) : "memory")
#define MBAR_EXPECT(a, b) asm volatile("mbarrier.arrive.expect_tx.shared.b64 _, [%0], %1;" :: "r"(a), "r"(b) : "memory")
#define MBAR_WAIT(a, ph) do { \
    uint32_t _m = (a), _p = (ph), _d; \
    asm volatile("{\n\t.reg .pred p;\n\tmbarrier.try_wait.parity.acquire.cta.shared::cta.b64 p, [%1], %2;\n\tselp.b32 %0, 1, 0, p;\n\t}" \
        : "=r"(_d) : "r"(_m), "r"(_p) : "memory"); \
    if (!_d) { \
        asm volatile("{\n\t.reg .pred P1;\n\tWL_%=:\n\tmbarrier.try_wait.parity.acquire.cta.shared::cta.b64 P1, [%0], %1, 0x989680;\n\t@P1 bra.uni WD_%=;\n\tbra.uni WL_%=;\n\tWD_%=:\n\t}" \
            :: "r"(_m), "r"(_p) : "memory"); \
    } } while (0)

__device__ __forceinline__ void bulk_g2s(uint32_t dst, const void* src, uint32_t bytes, uint32_t mbar) {
    asm volatile("cp.async.bulk.shared::cta.global.mbarrier::complete_tx::bytes [%0], [%1], %2, [%3];"
        :: "r"(dst), "l"(src), "r"(bytes), "r"(mbar) : "memory");
}

__device__ __forceinline__ void ldsm4(uint32_t* r, uint32_t addr) {
    asm volatile("ldmatrix.sync.aligned.m8n8.x4.shared.b16 {%0,%1,%2,%3}, [%4];"
        : "=r"(r[0]), "=r"(r[1]), "=r"(r[2]), "=r"(r[3]) : "r"(addr));
}
__device__ __forceinline__ void ldsm2(uint32_t* r, uint32_t addr) {
    asm volatile("ldmatrix.sync.aligned.m8n8.x2.shared.b16 {%0,%1}, [%2];"
        : "=r"(r[0]), "=r"(r[1]) : "r"(addr));
}
__device__ __forceinline__ void mma16816(float* c, const uint32_t* a, const uint32_t* b) {
    asm volatile("mma.sync.aligned.m16n8k16.row.col.f32.bf16.bf16.f32 "
        "{%0,%1,%2,%3}, {%4,%5,%6,%7}, {%8,%9}, {%0,%1,%2,%3};"
        : "+f"(c[0]), "+f"(c[1]), "+f"(c[2]), "+f"(c[3])
        : "r"(a[0]), "r"(a[1]), "r"(a[2]), "r"(a[3]), "r"(b[0]), "r"(b[1]));
}
// pack two floats as bf16x2: low 16 bits = first arg
__device__ __forceinline__ uint32_t pack_bf2(float lo_e, float hi_e) {
    uint32_t r;
    asm("cvt.rn.bf16x2.f32 %0, %1, %2;" : "=r"(r) : "f"(hi_e), "f"(lo_e));
    return r;
}

// ---------------- CSR build ----------------
__global__ void k_zero() {
    int i = blockIdx.x * blockDim.x + threadIdx.x;
    if (i < NN) g_deg[i] = 0;
}
__global__ void k_count(const int* __restrict__ dst) {
    int e = blockIdx.x * blockDim.x + threadIdx.x;
    if (e < NE) atomicAdd(&g_deg[dst[e]], 1);
}
__global__ void k_scan_block() {
    __shared__ int s[1024];
    int tid = threadIdx.x;
    int i = blockIdx.x * 1024 + tid;
    int v = (i < NN) ? g_deg[i] : 0;
    s[tid] = v;
    __syncthreads();
    for (int off = 1; off < 1024; off <<= 1) {
        int t = (tid >= off) ? s[tid - off] : 0;
        __syncthreads();
        s[tid] += t;
        __syncthreads();
    }
    if (i < NN) g_rowstart[i] = s[tid] - v;
    if (tid == 1023) g_bsum[blockIdx.x] = s[1023];
}
__global__ void k_scan_top() {
    __shared__ int s[128];
    int tid = threadIdx.x;
    int v = (tid < (NN + 1023) / 1024) ? g_bsum[tid] : 0;
    s[tid] = v;
    __syncthreads();
    for (int off = 1; off < 128; off <<= 1) {
        int t = (tid >= off) ? s[tid - off] : 0;
        __syncthreads();
        s[tid] += t;
        __syncthreads();
    }
    g_boff[tid] = s[tid] - v;
}
__global__ void k_scan_add() {
    int i = blockIdx.x * blockDim.x + threadIdx.x;
    if (i < NN) {
        int r = g_rowstart[i] + g_boff[i >> 10];
        g_rowstart[i] = r;
        g_cursor[i] = r;
    }
    if (i == 0) g_rowstart[NN] = NE;
}
__global__ void k_scatter(const int* __restrict__ src, const int* __restrict__ dst) {
    int e = blockIdx.x * blockDim.x + threadIdx.x;
    if (e < NE) {
        int p = atomicAdd(&g_cursor[dst[e]], 1);
        g_csr[p] = src[e];
    }
}

// ---------------- embedding gather ----------------
__global__ void k_gather(const int* __restrict__ x, const float* __restrict__ emb) {
    int idx = blockIdx.x * blockDim.x + threadIdx.x;
    if (idx < NN * 32) {
        int node = idx >> 5, q = idx & 31;
        ((float4*)g_hA)[(size_t)node * 32 + q] = ((const float4*)emb)[(size_t)x[node] * 32 + q];
    }
}

// ---------------- weight transpose + bf16 hi/lo split ----------------
// 10 blocks (layer, a/b); out images are [n][k] bf16, pitch 272B.
__global__ void k_wconv(const float* __restrict__ Wa, const float* __restrict__ Wb) {
    extern __shared__ float tile[];   // 128 x 129
    int l = blockIdx.x >> 1;
    int m = blockIdx.x & 1;
    const float* W = (m == 0 ? Wa : Wb) + (size_t)l * 16384;
    int tid = threadIdx.x;
    for (int idx = tid; idx < 16384; idx += 256)
        tile[(idx >> 7) * 129 + (idx & 127)] = W[idx];   // tile[k][n]
    __syncthreads();
    int wid = tid >> 5, lane = tid & 31;
    unsigned char* hiImg = g_Wt + ((size_t)l * 4 + (size_t)m * 2) * IMG;
    unsigned char* loImg = hiImg + IMG;
    for (int i = 0; i < 16; i++) {
        int n = wid * 16 + i;
        int k0 = lane * 4;
        float w0 = tile[(k0 + 0) * 129 + n];
        float w1 = tile[(k0 + 1) * 129 + n];
        float w2 = tile[(k0 + 2) * 129 + n];
        float w3 = tile[(k0 + 3) * 129 + n];
        float h0 = __bfloat162float(__float2bfloat16_rn(w0));
        float h1 = __bfloat162float(__float2bfloat16_rn(w1));
        float h2 = __bfloat162float(__float2bfloat16_rn(w2));
        float h3 = __bfloat162float(__float2bfloat16_rn(w3));
        uint2 hv = make_uint2(pack_bf2(h0, h1), pack_bf2(h2, h3));
        uint2 lv = make_uint2(pack_bf2(w0 - h0, w1 - h1), pack_bf2(w2 - h2, w3 - h3));
        *(uint2*)(hiImg + n * PITCH + lane * 8) = hv;
        *(uint2*)(loImg + n * PITCH + lane * 8) = lv;
    }
}

// ---------------- fused GIN layer: agg + 2x bf16x3 mma.sync GEMM ----------------
__global__ void __launch_bounds__(256, 1) k_layer(
    const float* __restrict__ h_in, float* __restrict__ h_out,
    const unsigned char* __restrict__ Wt,
    const float* __restrict__ ba, const float* __restrict__ bb)
{
    extern __shared__ char smem[];
    const uint32_t sb = smem_u32(smem);
    float* ba_s = (float*)(smem + SM_BA);
    float* bb_s = (float*)(smem + SM_BB);
    const int tid = threadIdx.x;
    const int wid = tid >> 5;
    const int lane = tid & 31;
    const int base = blockIdx.x * TILE_M;
    const int m0 = wid * 16;

    if (tid == 0) MBAR_INIT(sb + SM_MBAR, 1);
    if (tid < 128) { ba_s[tid] = ba[tid]; bb_s[tid] = bb[tid]; }
    __syncthreads();
    if (tid == 0) {
        MBAR_EXPECT(sb + SM_MBAR, WBYTES);
        bulk_g2s(sb + SM_B, Wt, WBYTES, sb + SM_MBAR);
    }

    // ---- aggregation: rows m0..m0+15 (this warp's own rows), split to bf16 hi/lo images
    for (int i = 0; i < 16; i++) {
        int ln = m0 + i;
        int gn = base + ln;
        float4 acc = make_float4(0.f, 0.f, 0.f, 0.f);
        if (gn < NN) {
            acc = ((const float4*)(h_in + (size_t)gn * DD))[lane];
            int j = g_rowstart[gn], end = g_rowstart[gn + 1];
            for (; j + 4 <= end; j += 4) {
                int s0 = g_csr[j], s1 = g_csr[j + 1], s2 = g_csr[j + 2], s3 = g_csr[j + 3];
                float4 v0 = ((const float4*)(h_in + (size_t)s0 * DD))[lane];
                float4 v1 = ((const float4*)(h_in + (size_t)s1 * DD))[lane];
                float4 v2 = ((const float4*)(h_in + (size_t)s2 * DD))[lane];
                float4 v3 = ((const float4*)(h_in + (size_t)s3 * DD))[lane];
                acc.x += (v0.x + v1.x) + (v2.x + v3.x);
                acc.y += (v0.y + v1.y) + (v2.y + v3.y);
                acc.z += (v0.z + v1.z) + (v2.z + v3.z);
                acc.w += (v0.w + v1.w) + (v2.w + v3.w);
            }
            for (; j < end; j++) {
                int s0 = g_csr[j];
                float4 v0 = ((const float4*)(h_in + (size_t)s0 * DD))[lane];
                acc.x += v0.x; acc.y += v0.y; acc.z += v0.z; acc.w += v0.w;
            }
        }
        float hx = __bfloat162float(__float2bfloat16_rn(acc.x));
        float hy = __bfloat162float(__float2bfloat16_rn(acc.y));
        float hz = __bfloat162float(__float2bfloat16_rn(acc.z));
        float hw = __bfloat162float(__float2bfloat16_rn(acc.w));
        uint2 hv = make_uint2(pack_bf2(hx, hy), pack_bf2(hz, hw));
        uint2 lv = make_uint2(pack_bf2(acc.x - hx, acc.y - hy), pack_bf2(acc.z - hz, acc.w - hw));
        *(uint2*)(smem + SM_A  + ln * PITCH + lane * 8) = hv;
        *(uint2*)(smem + SM_AL + ln * PITCH + lane * 8) = lv;
    }
    __syncwarp();
    MBAR_WAIT(sb + SM_MBAR, 0);

    // per-thread ldmatrix addresses
    const uint32_t aBase = sb + SM_A + (uint32_t)(m0 + (lane & 15)) * PITCH + ((lane >> 4) << 4);
    const uint32_t bLane = (uint32_t)(lane & 7) * PITCH + (((lane >> 3) & 1) << 4);
    const int colq = (lane & 3) * 2;
    const int rq = lane >> 2;

    // ================= GEMM1: t = relu(z3 @ Wa3 + ba) =================
    {
        uint32_t aH[8][4], aL[8][4];
        #pragma unroll
        for (int ks = 0; ks < 8; ks++) {
            ldsm4(aH[ks], aBase + ks * 32);
            ldsm4(aL[ks], aBase + IMG + ks * 32);
        }
        const uint32_t bHB = sb + SM_B;           // WaH
        const uint32_t bLB = sb + SM_B + IMG;     // WaL
        #pragma unroll 1
        for (int nt = 0; nt < 16; nt++) {
            int n0 = nt * 8;
            float c[4] = {0.f, 0.f, 0.f, 0.f};
            uint32_t bo = (uint32_t)n0 * PITCH + bLane;
            #pragma unroll
            for (int ks = 0; ks < 8; ks++) {
                uint32_t bH[2], bL[2];
                ldsm2(bH, bHB + bo + ks * 32);
                ldsm2(bL, bLB + bo + ks * 32);
                mma16816(c, aH[ks], bH);
                mma16816(c, aH[ks], bL);
                mma16816(c, aL[ks], bH);
            }
            // epilogue 1: bias + relu, split, overwrite A images
            int col = n0 + colq;
            float b0 = ba_s[col], b1 = ba_s[col + 1];
            float t00 = fmaxf(c[0] + b0, 0.f), t01 = fmaxf(c[1] + b1, 0.f);
            float t10 = fmaxf(c[2] + b0, 0.f), t11 = fmaxf(c[3] + b1, 0.f);
            float h00 = __bfloat162float(__float2bfloat16_rn(t00));
            float h01 = __bfloat162float(__float2bfloat16_rn(t01));
            float h10 = __bfloat162float(__float2bfloat16_rn(t10));
            float h11 = __bfloat162float(__float2bfloat16_rn(t11));
            uint32_t o0 = (uint32_t)(m0 + rq) * PITCH + (uint32_t)col * 2;
            uint32_t o1 = (uint32_t)(m0 + 8 + rq) * PITCH + (uint32_t)col * 2;
            *(uint32_t*)(smem + SM_A  + o0) = pack_bf2(h00, h01);
            *(uint32_t*)(smem + SM_A  + o1) = pack_bf2(h10, h11);
            *(uint32_t*)(smem + SM_AL + o0) = pack_bf2(t00 - h00, t01 - h01);
            *(uint32_t*)(smem + SM_AL + o1) = pack_bf2(t10 - h10, t11 - h11);
        }
    }
    __syncwarp();

    // ================= GEMM2: h' = relu(t3 @ Wb3 + bb) -> global =================
    {
        uint32_t aH[8][4], aL[8][4];
        #pragma unroll
        for (int ks = 0; ks < 8; ks++) {
            ldsm4(aH[ks], aBase + ks * 32);
            ldsm4(aL[ks], aBase + IMG + ks * 32);
        }
        const uint32_t bHB = sb + SM_B + 2 * IMG; // WbH
        const uint32_t bLB = sb + SM_B + 3 * IMG; // WbL
        int gr0 = base + m0 + rq;
        int gr1 = gr0 + 8;
        #pragma unroll 1
        for (int nt = 0; nt < 16; nt++) {
            int n0 = nt * 8;
            float c[4] = {0.f, 0.f, 0.f, 0.f};
            uint32_t bo = (uint32_t)n0 * PITCH + bLane;
            #pragma unroll
            for (int ks = 0; ks < 8; ks++) {
                uint32_t bH[2], bL[2];
                ldsm2(bH, bHB + bo + ks * 32);
                ldsm2(bL, bLB + bo + ks * 32);
                mma16816(c, aH[ks], bH);
                mma16816(c, aH[ks], bL);
                mma16816(c, aL[ks], bH);
            }
            int col = n0 + colq;
            float b0 = bb_s[col], b1 = bb_s[col + 1];
            if (gr0 < NN) {
                float2 o;
                o.x = fmaxf(c[0] + b0, 0.f);
                o.y = fmaxf(c[1] + b1, 0.f);
                *(float2*)(h_out + (size_t)gr0 * DD + col) = o;
            }
            if (gr1 < NN) {
                float2 o;
                o.x = fmaxf(c[2] + b0, 0.f);
                o.y = fmaxf(c[3] + b1, 0.f);
                *(float2*)(h_out + (size_t)gr1 * DD + col) = o;
            }
        }
    }
}

// ---------------- pooling + head ----------------
__global__ void k_pool(const float* __restrict__ h) {
    int c = threadIdx.x;
    float acc = 0.f;
    for (int i = blockIdx.x; i < NN; i += gridDim.x)
        acc += h[(size_t)i * DD + c];
    g_pp[blockIdx.x * DD + c] = acc;
}
__global__ void k_final(const float* __restrict__ Wlin, const float* __restrict__ blin,
                        float* __restrict__ out) {
    __shared__ float p[DD];
    int c = threadIdx.x;
    float acc = 0.f;
    for (int b = 0; b < 256; b++) acc += g_pp[b * DD + c];
    p[c] = acc;
    __syncthreads();
    float o = blin[c];
    #pragma unroll 8
    for (int k = 0; k < DD; k++) o += p[k] * Wlin[k * DD + c];
    out[c] = o;
}

// ---------------- launch ----------------
extern "C" void kernel_launch(void* const* d_in, const int* in_sizes, int n_in,
                              void* d_out, int out_size) {
    const int*   x    = (const int*)d_in[0];
    const int*   ei   = (const int*)d_in[1];
    const float* emb  = (const float*)d_in[2];
    const float* Wa   = (const float*)d_in[3];
    const float* ba   = (const float*)d_in[4];
    const float* Wb   = (const float*)d_in[5];
    const float* bb   = (const float*)d_in[6];
    const float* Wlin = (const float*)d_in[7];
    const float* blin = (const float*)d_in[8];
    float* out = (float*)d_out;

    const int* src = ei;
    const int* dst = ei + NE;

    cudaFuncSetAttribute(k_layer, cudaFuncAttributeMaxDynamicSharedMemorySize, SM_TOTAL);
    cudaFuncSetAttribute(k_wconv, cudaFuncAttributeMaxDynamicSharedMemorySize, 128 * 129 * 4);

    // CSR build
    k_zero<<<(NN + 255) / 256, 256>>>();
    k_count<<<(NE + 255) / 256, 256>>>(dst);
    k_scan_block<<<(NN + 1023) / 1024, 1024>>>();
    k_scan_top<<<1, 128>>>();
    k_scan_add<<<(NN + 255) / 256, 256>>>();
    k_scatter<<<(NE + 255) / 256, 256>>>(src, dst);

    // weight transpose/split + embedding gather
    k_wconv<<<NLAYER * 2, 256, 128 * 129 * 4>>>(Wa, Wb);
    k_gather<<<(NN * 32 + 255) / 256, 256>>>(x, emb);

    // layers (ping-pong)
    void *pA, *pB, *pW;
    cudaGetSymbolAddress(&pA, g_hA);
    cudaGetSymbolAddress(&pB, g_hB);
    cudaGetSymbolAddress(&pW, g_Wt);
    float* hbuf[2] = {(float*)pA, (float*)pB};
    const unsigned char* Wt = (const unsigned char*)pW;
    int cur = 0;
    for (int l = 0; l < NLAYER; l++) {
        k_layer<<<NBLK, 256, SM_TOTAL>>>(hbuf[cur], hbuf[1 - cur],
                                         Wt + (size_t)l * 4 * IMG,
                                         ba + (size_t)l * DD, bb + (size_t)l * DD);
        cur ^= 1;
    }

    // pool + head
    k_pool<<<256, 128>>>(hbuf[cur]);
    k_final<<<1, 128>>>(Wlin, blin, out);
}

// round 7
// speedup vs baseline: 2.6259x; 1.4390x over previous
#include <cuda_runtime.h>
#include <cuda_bf16.h>
#include <cstdint>

#define NN 100000
#define NE 600000
#define DD 128
#define NLAYER 5
#define TILE_M 256
#define NBLK ((NN + TILE_M - 1) / TILE_M)

#define PITCH 272                       // bytes per 128-bf16 row (256 + 16 pad)
#define IMG   (128 * PITCH)             // 34816 bytes per weight image
#define AIMG  (TILE_M * PITCH)          // 69632 bytes per A image
#define WPAIR (2 * IMG)                 // hi+lo pair = 69632

// SMEM layout (bytes)
#define SM_MBAR0 0
#define SM_MBAR1 8
#define SM_BA   16
#define SM_BB   528
#define SM_A    1088                    // A_hi image (256 rows)
#define SM_AL   (SM_A + AIMG)           // A_lo image
#define SM_W    (SM_AL + AIMG)          // weight pair buffer (hi|lo)
#define SM_TOTAL (SM_W + WPAIR)         // 209984

// ---------------- scratch ----------------
__device__ __align__(128) float g_hA[NN * DD];
__device__ __align__(128) float g_hB[NN * DD];
__device__ int   g_deg[NN];
__device__ int   g_rowstart[NN + 1];
__device__ int   g_cursor[NN];
__device__ int   g_csr[NE];
__device__ int   g_bsum[128];
__device__ int   g_boff[128];
__device__ float g_pp[256 * DD];
__device__ __align__(128) unsigned char g_Wt[NLAYER * 4 * IMG];  // [WaH|WaL|WbH|WbL] per layer

// ---------------- helpers ----------------
__device__ __forceinline__ uint32_t smem_u32(const void* p) {
    uint32_t a;
    asm("{ .reg .u64 t; cvta.to.shared.u64 t, %1; cvt.u32.u64 %0, t; }" : "=r"(a) : "l"(p));
    return a;
}
#define MBAR_INIT(a, c) asm volatile("mbarrier.init.shared.b64 [%0], %1;" :: "r"(a), "r"(c) : "memory")
#define MBAR_EXPECT(a, b) asm volatile("mbarrier.arrive.expect_tx.shared.b64 _, [%0], %1;" :: "r"(a), "r"(b) : "memory")
#define MBAR_WAIT(a, ph) do { \
    uint32_t _m = (a), _p = (ph), _d; \
    asm volatile("{\n\t.reg .pred p;\n\tmbarrier.try_wait.parity.acquire.cta.shared::cta.b64 p, [%1], %2;\n\tselp.b32 %0, 1, 0, p;\n\t}" \
        : "=r"(_d) : "r"(_m), "r"(_p) : "memory"); \
    if (!_d) { \
        asm volatile("{\n\t.reg .pred P1;\n\tWL_%=:\n\tmbarrier.try_wait.parity.acquire.cta.shared::cta.b64 P1, [%0], %1, 0x989680;\n\t@P1 bra.uni WD_%=;\n\tbra.uni WL_%=;\n\tWD_%=:\n\t}" \
            :: "r"(_m), "r"(_p) : "memory"); \
    } } while (0)

__device__ __forceinline__ void bulk_g2s(uint32_t dst, const void* src, uint32_t bytes, uint32_t mbar) {
    asm volatile("cp.async.bulk.shared::cta.global.mbarrier::complete_tx::bytes [%0], [%1], %2, [%3];"
        :: "r"(dst), "l"(src), "r"(bytes), "r"(mbar) : "memory");
}

__device__ __forceinline__ void ldsm4(uint32_t* r, uint32_t addr) {
    asm volatile("ldmatrix.sync.aligned.m8n8.x4.shared.b16 {%0,%1,%2,%3}, [%4];"
        : "=r"(r[0]), "=r"(r[1]), "=r"(r[2]), "=r"(r[3]) : "r"(addr));
}
__device__ __forceinline__ void ldsm2(uint32_t* r, uint32_t addr) {
    asm volatile("ldmatrix.sync.aligned.m8n8.x2.shared.b16 {%0,%1}, [%2];"
        : "=r"(r[0]), "=r"(r[1]) : "r"(addr));
}
__device__ __forceinline__ void mma16816(float* c, const uint32_t* a, const uint32_t* b) {
    asm volatile("mma.sync.aligned.m16n8k16.row.col.f32.bf16.bf16.f32 "
        "{%0,%1,%2,%3}, {%4,%5,%6,%7}, {%8,%9}, {%0,%1,%2,%3};"
        : "+f"(c[0]), "+f"(c[1]), "+f"(c[2]), "+f"(c[3])
        : "r"(a[0]), "r"(a[1]), "r"(a[2]), "r"(a[3]), "r"(b[0]), "r"(b[1]));
}
// pack two floats as bf16x2: low 16 bits = first arg
__device__ __forceinline__ uint32_t pack_bf2(float lo_e, float hi_e) {
    uint32_t r;
    asm("cvt.rn.bf16x2.f32 %0, %1, %2;" : "=r"(r) : "f"(hi_e), "f"(lo_e));
    return r;
}

// ---------------- CSR build ----------------
__global__ void k_zero() {
    int i = blockIdx.x * blockDim.x + threadIdx.x;
    if (i < NN) g_deg[i] = 0;
}
__global__ void k_count(const int* __restrict__ dst) {
    int e = blockIdx.x * blockDim.x + threadIdx.x;
    if (e < NE) atomicAdd(&g_deg[dst[e]], 1);
}
__global__ void k_scan_block() {
    __shared__ int s[1024];
    int tid = threadIdx.x;
    int i = blockIdx.x * 1024 + tid;
    int v = (i < NN) ? g_deg[i] : 0;
    s[tid] = v;
    __syncthreads();
    for (int off = 1; off < 1024; off <<= 1) {
        int t = (tid >= off) ? s[tid - off] : 0;
        __syncthreads();
        s[tid] += t;
        __syncthreads();
    }
    if (i < NN) g_rowstart[i] = s[tid] - v;
    if (tid == 1023) g_bsum[blockIdx.x] = s[1023];
}
__global__ void k_scan_top() {
    __shared__ int s[128];
    int tid = threadIdx.x;
    int v = (tid < (NN + 1023) / 1024) ? g_bsum[tid] : 0;
    s[tid] = v;
    __syncthreads();
    for (int off = 1; off < 128; off <<= 1) {
        int t = (tid >= off) ? s[tid - off] : 0;
        __syncthreads();
        s[tid] += t;
        __syncthreads();
    }
    g_boff[tid] = s[tid] - v;
}
__global__ void k_scan_add() {
    int i = blockIdx.x * blockDim.x + threadIdx.x;
    if (i < NN) {
        int r = g_rowstart[i] + g_boff[i >> 10];
        g_rowstart[i] = r;
        g_cursor[i] = r;
    }
    if (i == 0) g_rowstart[NN] = NE;
}
__global__ void k_scatter(const int* __restrict__ src, const int* __restrict__ dst) {
    int e = blockIdx.x * blockDim.x + threadIdx.x;
    if (e < NE) {
        int p = atomicAdd(&g_cursor[dst[e]], 1);
        g_csr[p] = src[e];
    }
}

// ---------------- embedding gather ----------------
__global__ void k_gather(const int* __restrict__ x, const float* __restrict__ emb) {
    int idx = blockIdx.x * blockDim.x + threadIdx.x;
    if (idx < NN * 32) {
        int node = idx >> 5, q = idx & 31;
        ((float4*)g_hA)[(size_t)node * 32 + q] = ((const float4*)emb)[(size_t)x[node] * 32 + q];
    }
}

// ---------------- weight transpose + bf16 hi/lo split ----------------
// 40 blocks: (layer, a/b, n-quarter). Output images [n][k] bf16, pitch 272B.
__global__ void k_wconv(const float* __restrict__ Wa, const float* __restrict__ Wb) {
    __shared__ float tile[128 * 33];     // [k][n_local]
    int b = blockIdx.x;
    int l = b >> 3;
    int m = (b >> 2) & 1;
    int q = b & 3;
    int n0 = q * 32;
    const float* W = (m == 0 ? Wa : Wb) + (size_t)l * 16384;
    int tid = threadIdx.x;
    for (int idx = tid; idx < 128 * 32; idx += 256) {
        int k = idx >> 5, nn = idx & 31;
        tile[k * 33 + nn] = W[k * 128 + n0 + nn];
    }
    __syncthreads();
    int wid = tid >> 5, lane = tid & 31;
    unsigned char* hiImg = g_Wt + ((size_t)l * 4 + (size_t)m * 2) * IMG;
    unsigned char* loImg = hiImg + IMG;
    for (int i = 0; i < 4; i++) {
        int nl = wid * 4 + i;
        int n = n0 + nl;
        int k0 = lane * 4;
        float w0 = tile[(k0 + 0) * 33 + nl];
        float w1 = tile[(k0 + 1) * 33 + nl];
        float w2 = tile[(k0 + 2) * 33 + nl];
        float w3 = tile[(k0 + 3) * 33 + nl];
        float h0 = __bfloat162float(__float2bfloat16_rn(w0));
        float h1 = __bfloat162float(__float2bfloat16_rn(w1));
        float h2 = __bfloat162float(__float2bfloat16_rn(w2));
        float h3 = __bfloat162float(__float2bfloat16_rn(w3));
        uint2 hv = make_uint2(pack_bf2(h0, h1), pack_bf2(h2, h3));
        uint2 lv = make_uint2(pack_bf2(w0 - h0, w1 - h1), pack_bf2(w2 - h2, w3 - h3));
        *(uint2*)(hiImg + n * PITCH + lane * 8) = hv;
        *(uint2*)(loImg + n * PITCH + lane * 8) = lv;
    }
}

// ---------------- fused GIN layer: agg + 2x bf16x3 mma.sync GEMM ----------------
// 512 threads, 16 warps, each warp owns 16 rows end-to-end. Weights double-buffered.
__global__ void __launch_bounds__(512, 1) k_layer(
    const float* __restrict__ h_in, float* __restrict__ h_out,
    const unsigned char* __restrict__ Wt,   // [WaH|WaL|WbH|WbL]
    const float* __restrict__ ba, const float* __restrict__ bb)
{
    extern __shared__ char smem[];
    const uint32_t sb = smem_u32(smem);
    float* ba_s = (float*)(smem + SM_BA);
    float* bb_s = (float*)(smem + SM_BB);
    const int tid = threadIdx.x;
    const int wid = tid >> 5;
    const int lane = tid & 31;
    const int base = blockIdx.x * TILE_M;
    const int m0 = wid * 16;

    if (tid == 0) { MBAR_INIT(sb + SM_MBAR0, 1); MBAR_INIT(sb + SM_MBAR1, 1); }
    if (tid < 128) { ba_s[tid] = ba[tid]; bb_s[tid] = bb[tid]; }
    __syncthreads();
    if (tid == 0) {
        MBAR_EXPECT(sb + SM_MBAR0, WPAIR);
        bulk_g2s(sb + SM_W, Wt, WPAIR, sb + SM_MBAR0);   // WaH|WaL
    }

    // ---- aggregation: rows m0..m0+15 (warp-private), split to bf16 hi/lo A images
    for (int i = 0; i < 16; i++) {
        int ln = m0 + i;
        int gn = base + ln;
        float4 acc = make_float4(0.f, 0.f, 0.f, 0.f);
        if (gn < NN) {
            acc = ((const float4*)(h_in + (size_t)gn * DD))[lane];
            int j = g_rowstart[gn], end = g_rowstart[gn + 1];
            for (; j + 4 <= end; j += 4) {
                int s0 = g_csr[j], s1 = g_csr[j + 1], s2 = g_csr[j + 2], s3 = g_csr[j + 3];
                float4 v0 = ((const float4*)(h_in + (size_t)s0 * DD))[lane];
                float4 v1 = ((const float4*)(h_in + (size_t)s1 * DD))[lane];
                float4 v2 = ((const float4*)(h_in + (size_t)s2 * DD))[lane];
                float4 v3 = ((const float4*)(h_in + (size_t)s3 * DD))[lane];
                acc.x += (v0.x + v1.x) + (v2.x + v3.x);
                acc.y += (v0.y + v1.y) + (v2.y + v3.y);
                acc.z += (v0.z + v1.z) + (v2.z + v3.z);
                acc.w += (v0.w + v1.w) + (v2.w + v3.w);
            }
            for (; j < end; j++) {
                int s0 = g_csr[j];
                float4 v0 = ((const float4*)(h_in + (size_t)s0 * DD))[lane];
                acc.x += v0.x; acc.y += v0.y; acc.z += v0.z; acc.w += v0.w;
            }
        }
        float hx = __bfloat162float(__float2bfloat16_rn(acc.x));
        float hy = __bfloat162float(__float2bfloat16_rn(acc.y));
        float hz = __bfloat162float(__float2bfloat16_rn(acc.z));
        float hw = __bfloat162float(__float2bfloat16_rn(acc.w));
        uint2 hv = make_uint2(pack_bf2(hx, hy), pack_bf2(hz, hw));
        uint2 lv = make_uint2(pack_bf2(acc.x - hx, acc.y - hy), pack_bf2(acc.z - hz, acc.w - hw));
        *(uint2*)(smem + SM_A  + ln * PITCH + lane * 8) = hv;
        *(uint2*)(smem + SM_AL + ln * PITCH + lane * 8) = lv;
    }
    __syncwarp();
    MBAR_WAIT(sb + SM_MBAR0, 0);     // Wa pair resident

    // per-thread ldmatrix addresses
    const uint32_t aBase = sb + SM_A + (uint32_t)(m0 + (lane & 15)) * PITCH + ((lane >> 4) << 4);
    const uint32_t bLane = (uint32_t)(lane & 7) * PITCH + (((lane >> 3) & 1) << 4);
    const int colq = (lane & 3) * 2;
    const int rq = lane >> 2;

    // ================= GEMM1: t = relu(z3 @ Wa3 + ba) =================
    {
        uint32_t aH[8][4], aL[8][4];
        #pragma unroll
        for (int ks = 0; ks < 8; ks++) {
            ldsm4(aH[ks], aBase + ks * 32);
            ldsm4(aL[ks], aBase + AIMG + ks * 32);
        }
        const uint32_t bHB = sb + SM_W;           // WaH
        const uint32_t bLB = sb + SM_W + IMG;     // WaL
        #pragma unroll 1
        for (int nt = 0; nt < 16; nt++) {
            int n0 = nt * 8;
            float c[4] = {0.f, 0.f, 0.f, 0.f};
            uint32_t bo = (uint32_t)n0 * PITCH + bLane;
            #pragma unroll
            for (int ks = 0; ks < 8; ks++) {
                uint32_t bH[2], bL[2];
                ldsm2(bH, bHB + bo + ks * 32);
                ldsm2(bL, bLB + bo + ks * 32);
                mma16816(c, aH[ks], bH);
                mma16816(c, aH[ks], bL);
                mma16816(c, aL[ks], bH);
            }
            // epilogue 1: bias + relu, split, overwrite A images (own rows)
            int col = n0 + colq;
            float b0 = ba_s[col], b1 = ba_s[col + 1];
            float t00 = fmaxf(c[0] + b0, 0.f), t01 = fmaxf(c[1] + b1, 0.f);
            float t10 = fmaxf(c[2] + b0, 0.f), t11 = fmaxf(c[3] + b1, 0.f);
            float h00 = __bfloat162float(__float2bfloat16_rn(t00));
            float h01 = __bfloat162float(__float2bfloat16_rn(t01));
            float h10 = __bfloat162float(__float2bfloat16_rn(t10));
            float h11 = __bfloat162float(__float2bfloat16_rn(t11));
            uint32_t o0 = (uint32_t)(m0 + rq) * PITCH + (uint32_t)col * 2;
            uint32_t o1 = (uint32_t)(m0 + 8 + rq) * PITCH + (uint32_t)col * 2;
            *(uint32_t*)(smem + SM_A  + o0) = pack_bf2(h00, h01);
            *(uint32_t*)(smem + SM_A  + o1) = pack_bf2(h10, h11);
            *(uint32_t*)(smem + SM_AL + o0) = pack_bf2(t00 - h00, t01 - h01);
            *(uint32_t*)(smem + SM_AL + o1) = pack_bf2(t10 - h10, t11 - h11);
        }
    }
    // all warps must finish reading Wa before Wb overwrites the buffer
    __syncthreads();
    if (tid == 0) {
        MBAR_EXPECT(sb + SM_MBAR1, WPAIR);
        bulk_g2s(sb + SM_W, Wt + WPAIR, WPAIR, sb + SM_MBAR1);   // WbH|WbL
    }
    MBAR_WAIT(sb + SM_MBAR1, 0);

    // ================= GEMM2: h' = relu(t3 @ Wb3 + bb) -> global =================
    {
        uint32_t aH[8][4], aL[8][4];
        #pragma unroll
        for (int ks = 0; ks < 8; ks++) {
            ldsm4(aH[ks], aBase + ks * 32);
            ldsm4(aL[ks], aBase + AIMG + ks * 32);
        }
        const uint32_t bHB = sb + SM_W;           // WbH
        const uint32_t bLB = sb + SM_W + IMG;     // WbL
        int gr0 = base + m0 + rq;
        int gr1 = gr0 + 8;
        #pragma unroll 1
        for (int nt = 0; nt < 16; nt++) {
            int n0 = nt * 8;
            float c[4] = {0.f, 0.f, 0.f, 0.f};
            uint32_t bo = (uint32_t)n0 * PITCH + bLane;
            #pragma unroll
            for (int ks = 0; ks < 8; ks++) {
                uint32_t bH[2], bL[2];
                ldsm2(bH, bHB + bo + ks * 32);
                ldsm2(bL, bLB + bo + ks * 32);
                mma16816(c, aH[ks], bH);
                mma16816(c, aH[ks], bL);
                mma16816(c, aL[ks], bH);
            }
            int col = n0 + colq;
            float b0 = bb_s[col], b1 = bb_s[col + 1];
            if (gr0 < NN) {
                float2 o;
                o.x = fmaxf(c[0] + b0, 0.f);
                o.y = fmaxf(c[1] + b1, 0.f);
                *(float2*)(h_out + (size_t)gr0 * DD + col) = o;
            }
            if (gr1 < NN) {
                float2 o;
                o.x = fmaxf(c[2] + b0, 0.f);
                o.y = fmaxf(c[3] + b1, 0.f);
                *(float2*)(h_out + (size_t)gr1 * DD + col) = o;
            }
        }
    }
}

// ---------------- pooling + head ----------------
__global__ void k_pool(const float* __restrict__ h) {
    int c = threadIdx.x;
    float acc = 0.f;
    #pragma unroll 8
    for (int i = blockIdx.x; i < NN; i += gridDim.x)
        acc += h[(size_t)i * DD + c];
    g_pp[blockIdx.x * DD + c] = acc;
}
__global__ void k_final(const float* __restrict__ Wlin, const float* __restrict__ blin,
                        float* __restrict__ out) {
    __shared__ float p[DD];
    int c = threadIdx.x;
    float acc = 0.f;
    for (int b = 0; b < 256; b++) acc += g_pp[b * DD + c];
    p[c] = acc;
    __syncthreads();
    float o = blin[c];
    #pragma unroll 8
    for (int k = 0; k < DD; k++) o += p[k] * Wlin[k * DD + c];
    out[c] = o;
}

// ---------------- launch ----------------
extern "C" void kernel_launch(void* const* d_in, const int* in_sizes, int n_in,
                              void* d_out, int out_size) {
    const int*   x    = (const int*)d_in[0];
    const int*   ei   = (const int*)d_in[1];
    const float* emb  = (const float*)d_in[2];
    const float* Wa   = (const float*)d_in[3];
    const float* ba   = (const float*)d_in[4];
    const float* Wb   = (const float*)d_in[5];
    const float* bb   = (const float*)d_in[6];
    const float* Wlin = (const float*)d_in[7];
    const float* blin = (const float*)d_in[8];
    float* out = (float*)d_out;

    const int* src = ei;
    const int* dst = ei + NE;

    cudaFuncSetAttribute(k_layer, cudaFuncAttributeMaxDynamicSharedMemorySize, SM_TOTAL);

    // CSR build
    k_zero<<<(NN + 255) / 256, 256>>>();
    k_count<<<(NE + 255) / 256, 256>>>(dst);
    k_scan_block<<<(NN + 1023) / 1024, 1024>>>();
    k_scan_top<<<1, 128>>>();
    k_scan_add<<<(NN + 255) / 256, 256>>>();
    k_scatter<<<(NE + 255) / 256, 256>>>(src, dst);

    // weight transpose/split + embedding gather
    k_wconv<<<NLAYER * 2 * 4, 256>>>(Wa, Wb);
    k_gather<<<(NN * 32 + 255) / 256, 256>>>(x, emb);

    // layers (ping-pong)
    void *pA, *pB, *pW;
    cudaGetSymbolAddress(&pA, g_hA);
    cudaGetSymbolAddress(&pB, g_hB);
    cudaGetSymbolAddress(&pW, g_Wt);
    float* hbuf[2] = {(float*)pA, (float*)pB};
    const unsigned char* Wt = (const unsigned char*)pW;
    int cur = 0;
    for (int l = 0; l < NLAYER; l++) {
        k_layer<<<NBLK, 512, SM_TOTAL>>>(hbuf[cur], hbuf[1 - cur],
                                         Wt + (size_t)l * 4 * IMG,
                                         ba + (size_t)l * DD, bb + (size_t)l * DD);
        cur ^= 1;
    }

    // pool + head
    k_pool<<<256, 128>>>(hbuf[cur]);
    k_final<<<1, 128>>>(Wlin, blin, out);
}

// round 13
// speedup vs baseline: 3.1645x; 1.2051x over previous
#include <cuda_runtime.h>
#include <cuda_bf16.h>
#include <cstdint>

#define NN 100000
#define NE 600000
#define DD 128
#define NLAYER 5
#define TILE_M 256
#define NBLK ((NN + TILE_M - 1) / TILE_M)
#define ZROWS (NBLK * TILE_M)           // 100096 rows in z images

#define PITCH 272                       // bytes per 128-bf16 row (256 + 16 pad)
#define IMG   (128 * PITCH)             // 34816 bytes per weight image
#define AIMG  (TILE_M * PITCH)          // 69632 bytes per A image
#define WPAIR (2 * IMG)                 // hi+lo pair = 69632

// SMEM layout (bytes)
#define SM_MBARA  0
#define SM_MBARW0 8
#define SM_MBARW1 16
#define SM_BA   32
#define SM_BB   544
#define SM_A    1088                    // A_hi image (256 rows)
#define SM_AL   (SM_A + AIMG)           // A_lo image
#define SM_W    (SM_AL + AIMG)          // weight pair buffer (hi|lo)
#define SM_TOTAL (SM_W + WPAIR)         // 209984 bytes

// ---------------- scratch ----------------
__device__ __align__(128) float g_hA[NN * DD];
__device__ __align__(128) float g_hB[NN * DD];
__device__ int   g_deg[NN];
__device__ int   g_rowstart[NN + 1];
__device__ int   g_cursor[NN];
__device__ int   g_csr[NE];
__device__ int   g_bsum[128];
__device__ int   g_boff[128];
__device__ float g_pp[256 * DD];
__device__ __align__(128) unsigned char g_Wt[NLAYER * 4 * IMG];  // [WaH|WaL|WbH|WbL] per layer
__device__ __align__(128) unsigned char g_zH[ZROWS * PITCH];     // z hi image
__device__ __align__(128) unsigned char g_zL[ZROWS * PITCH];     // z lo image

// ---------------- helpers ----------------
__device__ __forceinline__ uint32_t smem_u32(const void* p) {
    uint32_t a;
    asm("{ .reg .u64 t; cvta.to.shared.u64 t, %1; cvt.u32.u64 %0, t; }" : "=r"(a) : "l"(p));
    return a;
}
#define MBAR_INIT(a, c) asm volatile("mbarrier.init.shared.b64 [%0], %1;" :: "r"(a), "r"(c) : "memory")
#define MBAR_EXPECT(a, b) asm volatile("mbarrier.arrive.expect_tx.shared.b64 _, [%0], %1;" :: "r"(a), "r"(b) : "memory")
#define MBAR_WAIT(a, ph) do { \
    uint32_t _m = (a), _p = (ph), _d; \
    asm volatile("{\n\t.reg .pred p;\n\tmbarrier.try_wait.parity.acquire.cta.shared::cta.b64 p, [%1], %2;\n\tselp.b32 %0, 1, 0, p;\n\t}" \
        : "=r"(_d) : "r"(_m), "r"(_p) : "memory"); \
    if (!_d) { \
        asm volatile("{\n\t.reg .pred P1;\n\tWL_%=:\n\tmbarrier.try_wait.parity.acquire.cta.shared::cta.b64 P1, [%0], %1, 0x989680;\n\t@P1 bra.uni WD_%=;\n\tbra.uni WL_%=;\n\tWD_%=:\n\t}" \
            :: "r"(_m), "r"(_p) : "memory"); \
    } } while (0)

__device__ __forceinline__ void bulk_g2s(uint32_t dst, const void* src, uint32_t bytes, uint32_t mbar) {
    asm volatile("cp.async.bulk.shared::cta.global.mbarrier::complete_tx::bytes [%0], [%1], %2, [%3];"
        :: "r"(dst), "l"(src), "r"(bytes), "r"(mbar) : "memory");
}

__device__ __forceinline__ void ldsm4(uint32_t* r, uint32_t addr) {
    asm volatile("ldmatrix.sync.aligned.m8n8.x4.shared.b16 {%0,%1,%2,%3}, [%4];"
        : "=r"(r[0]), "=r"(r[1]), "=r"(r[2]), "=r"(r[3]) : "r"(addr));
}
__device__ __forceinline__ void ldsm2(uint32_t* r, uint32_t addr) {
    asm volatile("ldmatrix.sync.aligned.m8n8.x2.shared.b16 {%0,%1}, [%2];"
        : "=r"(r[0]), "=r"(r[1]) : "r"(addr));
}
__device__ __forceinline__ void mma16816(float* c, const uint32_t* a, const uint32_t* b) {
    asm volatile("mma.sync.aligned.m16n8k16.row.col.f32.bf16.bf16.f32 "
        "{%0,%1,%2,%3}, {%4,%5,%6,%7}, {%8,%9}, {%0,%1,%2,%3};"
        : "+f"(c[0]), "+f"(c[1]), "+f"(c[2]), "+f"(c[3])
        : "r"(a[0]), "r"(a[1]), "r"(a[2]), "r"(a[3]), "r"(b[0]), "r"(b[1]));
}
// pack two floats as bf16x2: low 16 bits = first arg
__device__ __forceinline__ uint32_t pack_bf2(float lo_e, float hi_e) {
    uint32_t r;
    asm("cvt.rn.bf16x2.f32 %0, %1, %2;" : "=r"(r) : "f"(hi_e), "f"(lo_e));
    return r;
}

// ---------------- CSR build ----------------
__global__ void k_zero() {
    int i = blockIdx.x * blockDim.x + threadIdx.x;
    if (i < NN) g_deg[i] = 0;
}
__global__ void k_count(const int* __restrict__ dst) {
    int e = blockIdx.x * blockDim.x + threadIdx.x;
    if (e < NE) atomicAdd(&g_deg[dst[e]], 1);
}
__global__ void k_scan_block() {
    __shared__ int s[1024];
    int tid = threadIdx.x;
    int i = blockIdx.x * 1024 + tid;
    int v = (i < NN) ? g_deg[i] : 0;
    s[tid] = v;
    __syncthreads();
    for (int off = 1; off < 1024; off <<= 1) {
        int t = (tid >= off) ? s[tid - off] : 0;
        __syncthreads();
        s[tid] += t;
        __syncthreads();
    }
    if (i < NN) g_rowstart[i] = s[tid] - v;
    if (tid == 1023) g_bsum[blockIdx.x] = s[1023];
}
__global__ void k_scan_top() {
    __shared__ int s[128];
    int tid = threadIdx.x;
    int v = (tid < (NN + 1023) / 1024) ? g_bsum[tid] : 0;
    s[tid] = v;
    __syncthreads();
    for (int off = 1; off < 128; off <<= 1) {
        int t = (tid >= off) ? s[tid - off] : 0;
        __syncthreads();
        s[tid] += t;
        __syncthreads();
    }
    g_boff[tid] = s[tid] - v;
}
__global__ void k_scan_add() {
    int i = blockIdx.x * blockDim.x + threadIdx.x;
    if (i < NN) {
        int r = g_rowstart[i] + g_boff[i >> 10];
        g_rowstart[i] = r;
        g_cursor[i] = r;
    }
    if (i == 0) g_rowstart[NN] = NE;
}
__global__ void k_scatter(const int* __restrict__ src, const int* __restrict__ dst) {
    int e = blockIdx.x * blockDim.x + threadIdx.x;
    if (e < NE) {
        int p = atomicAdd(&g_cursor[dst[e]], 1);
        g_csr[p] = src[e];
    }
}

// ---------------- embedding gather ----------------
__global__ void k_gather(const int* __restrict__ x, const float* __restrict__ emb) {
    int idx = blockIdx.x * blockDim.x + threadIdx.x;
    if (idx < NN * 32) {
        int node = idx >> 5, q = idx & 31;
        ((float4*)g_hA)[(size_t)node * 32 + q] = ((const float4*)emb)[(size_t)x[node] * 32 + q];
    }
}

// ---------------- weight transpose + bf16 hi/lo split ----------------
__global__ void k_wconv(const float* __restrict__ Wa, const float* __restrict__ Wb) {
    __shared__ float tile[128 * 33];     // [k][n_local]
    int b = blockIdx.x;
    int l = b >> 3;
    int m = (b >> 2) & 1;
    int q = b & 3;
    int n0 = q * 32;
    const float* W = (m == 0 ? Wa : Wb) + (size_t)l * 16384;
    int tid = threadIdx.x;
    for (int idx = tid; idx < 128 * 32; idx += 256) {
        int k = idx >> 5, nn = idx & 31;
        tile[k * 33 + nn] = W[k * 128 + n0 + nn];
    }
    __syncthreads();
    int wid = tid >> 5, lane = tid & 31;
    unsigned char* hiImg = g_Wt + ((size_t)l * 4 + (size_t)m * 2) * IMG;
    unsigned char* loImg = hiImg + IMG;
    for (int i = 0; i < 4; i++) {
        int nl = wid * 4 + i;
        int n = n0 + nl;
        int k0 = lane * 4;
        float w0 = tile[(k0 + 0) * 33 + nl];
        float w1 = tile[(k0 + 1) * 33 + nl];
        float w2 = tile[(k0 + 2) * 33 + nl];
        float w3 = tile[(k0 + 3) * 33 + nl];
        float h0 = __bfloat162float(__float2bfloat16_rn(w0));
        float h1 = __bfloat162float(__float2bfloat16_rn(w1));
        float h2 = __bfloat162float(__float2bfloat16_rn(w2));
        float h3 = __bfloat162float(__float2bfloat16_rn(w3));
        uint2 hv = make_uint2(pack_bf2(h0, h1), pack_bf2(h2, h3));
        uint2 lv = make_uint2(pack_bf2(w0 - h0, w1 - h1), pack_bf2(w2 - h2, w3 - h3));
        *(uint2*)(hiImg + n * PITCH + lane * 8) = hv;
        *(uint2*)(loImg + n * PITCH + lane * 8) = lv;
    }
}

// ---------------- aggregation: warp-per-node, full occupancy ----------------
// z = h + sum_{j->i} h[src_j], split to bf16 hi/lo PITCH images in global.
__global__ void __launch_bounds__(256) k_agg(const float* __restrict__ h_in) {
    int row = blockIdx.x * 8 + (threadIdx.x >> 5);
    int lane = threadIdx.x & 31;
    if (row >= NN) return;
    float4 acc = ((const float4*)(h_in + (size_t)row * DD))[lane];
    int j = g_rowstart[row], end = g_rowstart[row + 1];
    for (; j + 4 <= end; j += 4) {
        int s0 = g_csr[j], s1 = g_csr[j + 1], s2 = g_csr[j + 2], s3 = g_csr[j + 3];
        float4 v0 = ((const float4*)(h_in + (size_t)s0 * DD))[lane];
        float4 v1 = ((const float4*)(h_in + (size_t)s1 * DD))[lane];
        float4 v2 = ((const float4*)(h_in + (size_t)s2 * DD))[lane];
        float4 v3 = ((const float4*)(h_in + (size_t)s3 * DD))[lane];
        acc.x += (v0.x + v1.x) + (v2.x + v3.x);
        acc.y += (v0.y + v1.y) + (v2.y + v3.y);
        acc.z += (v0.z + v1.z) + (v2.z + v3.z);
        acc.w += (v0.w + v1.w) + (v2.w + v3.w);
    }
    for (; j < end; j++) {
        int s0 = g_csr[j];
        float4 v0 = ((const float4*)(h_in + (size_t)s0 * DD))[lane];
        acc.x += v0.x; acc.y += v0.y; acc.z += v0.z; acc.w += v0.w;
    }
    float hx = __bfloat162float(__float2bfloat16_rn(acc.x));
    float hy = __bfloat162float(__float2bfloat16_rn(acc.y));
    float hz = __bfloat162float(__float2bfloat16_rn(acc.z));
    float hw = __bfloat162float(__float2bfloat16_rn(acc.w));
    uint2 hv = make_uint2(pack_bf2(hx, hy), pack_bf2(hz, hw));
    uint2 lv = make_uint2(pack_bf2(acc.x - hx, acc.y - hy), pack_bf2(acc.z - hz, acc.w - hw));
    *(uint2*)(g_zH + (size_t)row * PITCH + lane * 8) = hv;
    *(uint2*)(g_zL + (size_t)row * PITCH + lane * 8) = lv;
}

// ---------------- GEMM kernel: bulk-load z images + 2x bf16x3 mma.sync ----------------
__global__ void __launch_bounds__(512, 1) k_gemm(
    float* __restrict__ h_out,
    const unsigned char* __restrict__ Wt,   // [WaH|WaL|WbH|WbL]
    const float* __restrict__ ba, const float* __restrict__ bb)
{
    extern __shared__ char smem[];
    const uint32_t sb = smem_u32(smem);
    float* ba_s = (float*)(smem + SM_BA);
    float* bb_s = (float*)(smem + SM_BB);
    const int tid = threadIdx.x;
    const int wid = tid >> 5;
    const int lane = tid & 31;
    const int base = blockIdx.x * TILE_M;
    const int m0 = wid * 16;

    if (tid == 0) {
        MBAR_INIT(sb + SM_MBARA, 1);
        MBAR_INIT(sb + SM_MBARW0, 1);
        MBAR_INIT(sb + SM_MBARW1, 1);
    }
    if (tid < 128) { ba_s[tid] = ba[tid]; bb_s[tid] = bb[tid]; }
    __syncthreads();
    if (tid == 0) {
        MBAR_EXPECT(sb + SM_MBARA, 2u * AIMG);
        bulk_g2s(sb + SM_A,  g_zH + (size_t)base * PITCH, AIMG, sb + SM_MBARA);
        bulk_g2s(sb + SM_AL, g_zL + (size_t)base * PITCH, AIMG, sb + SM_MBARA);
        MBAR_EXPECT(sb + SM_MBARW0, WPAIR);
        bulk_g2s(sb + SM_W, Wt, WPAIR, sb + SM_MBARW0);   // WaH|WaL
    }
    MBAR_WAIT(sb + SM_MBARA, 0);
    MBAR_WAIT(sb + SM_MBARW0, 0);

    // per-thread ldmatrix addresses
    const uint32_t aBase = sb + SM_A + (uint32_t)(m0 + (lane & 15)) * PITCH + ((lane >> 4) << 4);
    const uint32_t bLane = (uint32_t)(lane & 7) * PITCH + (((lane >> 3) & 1) << 4);
    const int colq = (lane & 3) * 2;
    const int rq = lane >> 2;

    // ================= GEMM1: t = relu(z3 @ Wa3 + ba) =================
    {
        uint32_t aH[8][4], aL[8][4];
        #pragma unroll
        for (int ks = 0; ks < 8; ks++) {
            ldsm4(aH[ks], aBase + ks * 32);
            ldsm4(aL[ks], aBase + AIMG + ks * 32);
        }
        const uint32_t bHB = sb + SM_W;           // WaH
        const uint32_t bLB = sb + SM_W + IMG;     // WaL
        #pragma unroll 1
        for (int nt = 0; nt < 16; nt++) {
            int n0 = nt * 8;
            float c[4] = {0.f, 0.f, 0.f, 0.f};
            uint32_t bo = (uint32_t)n0 * PITCH + bLane;
            #pragma unroll
            for (int ks = 0; ks < 8; ks++) {
                uint32_t bH[2], bL[2];
                ldsm2(bH, bHB + bo + ks * 32);
                ldsm2(bL, bLB + bo + ks * 32);
                mma16816(c, aH[ks], bH);
                mma16816(c, aH[ks], bL);
                mma16816(c, aL[ks], bH);
            }
            // epilogue 1: bias + relu, split, overwrite A images (own rows)
            int col = n0 + colq;
            float b0 = ba_s[col], b1 = ba_s[col + 1];
            float t00 = fmaxf(c[0] + b0, 0.f), t01 = fmaxf(c[1] + b1, 0.f);
            float t10 = fmaxf(c[2] + b0, 0.f), t11 = fmaxf(c[3] + b1, 0.f);
            float h00 = __bfloat162float(__float2bfloat16_rn(t00));
            float h01 = __bfloat162float(__float2bfloat16_rn(t01));
            float h10 = __bfloat162float(__float2bfloat16_rn(t10));
            float h11 = __bfloat162float(__float2bfloat16_rn(t11));
            uint32_t o0 = (uint32_t)(m0 + rq) * PITCH + (uint32_t)col * 2;
            uint32_t o1 = (uint32_t)(m0 + 8 + rq) * PITCH + (uint32_t)col * 2;
            *(uint32_t*)(smem + SM_A  + o0) = pack_bf2(h00, h01);
            *(uint32_t*)(smem + SM_A  + o1) = pack_bf2(h10, h11);
            *(uint32_t*)(smem + SM_AL + o0) = pack_bf2(t00 - h00, t01 - h01);
            *(uint32_t*)(smem + SM_AL + o1) = pack_bf2(t10 - h10, t11 - h11);
        }
    }
    // all warps must finish reading Wa before Wb overwrites the buffer
    __syncthreads();
    if (tid == 0) {
        MBAR_EXPECT(sb + SM_MBARW1, WPAIR);
        bulk_g2s(sb + SM_W, Wt + WPAIR, WPAIR, sb + SM_MBARW1);   // WbH|WbL
    }
    MBAR_WAIT(sb + SM_MBARW1, 0);

    // ================= GEMM2: h' = relu(t3 @ Wb3 + bb) -> global =================
    {
        uint32_t aH[8][4], aL[8][4];
        #pragma unroll
        for (int ks = 0; ks < 8; ks++) {
            ldsm4(aH[ks], aBase + ks * 32);
            ldsm4(aL[ks], aBase + AIMG + ks * 32);
        }
        const uint32_t bHB = sb + SM_W;           // WbH
        const uint32_t bLB = sb + SM_W + IMG;     // WbL
        int gr0 = base + m0 + rq;
        int gr1 = gr0 + 8;
        #pragma unroll 1
        for (int nt = 0; nt < 16; nt++) {
            int n0 = nt * 8;
            float c[4] = {0.f, 0.f, 0.f, 0.f};
            uint32_t bo = (uint32_t)n0 * PITCH + bLane;
            #pragma unroll
            for (int ks = 0; ks < 8; ks++) {
                uint32_t bH[2], bL[2];
                ldsm2(bH, bHB + bo + ks * 32);
                ldsm2(bL, bLB + bo + ks * 32);
                mma16816(c, aH[ks], bH);
                mma16816(c, aH[ks], bL);
                mma16816(c, aL[ks], bH);
            }
            int col = n0 + colq;
            float b0 = bb_s[col], b1 = bb_s[col + 1];
            if (gr0 < NN) {
                float2 o;
                o.x = fmaxf(c[0] + b0, 0.f);
                o.y = fmaxf(c[1] + b1, 0.f);
                *(float2*)(h_out + (size_t)gr0 * DD + col) = o;
            }
            if (gr1 < NN) {
                float2 o;
                o.x = fmaxf(c[2] + b0, 0.f);
                o.y = fmaxf(c[3] + b1, 0.f);
                *(float2*)(h_out + (size_t)gr1 * DD + col) = o;
            }
        }
    }
}

// ---------------- pooling + head ----------------
__global__ void k_pool(const float* __restrict__ h) {
    int c = threadIdx.x;
    float acc = 0.f;
    #pragma unroll 8
    for (int i = blockIdx.x; i < NN; i += gridDim.x)
        acc += h[(size_t)i * DD + c];
    g_pp[blockIdx.x * DD + c] = acc;
}
__global__ void k_final(const float* __restrict__ Wlin, const float* __restrict__ blin,
                        float* __restrict__ out) {
    __shared__ float p[DD];
    int c = threadIdx.x;
    float acc = 0.f;
    for (int b = 0; b < 256; b++) acc += g_pp[b * DD + c];
    p[c] = acc;
    __syncthreads();
    float o = blin[c];
    #pragma unroll 8
    for (int k = 0; k < DD; k++) o += p[k] * Wlin[k * DD + c];
    out[c] = o;
}

// ---------------- launch ----------------
extern "C" void kernel_launch(void* const* d_in, const int* in_sizes, int n_in,
                              void* d_out, int out_size) {
    const int*   x    = (const int*)d_in[0];
    const int*   ei   = (const int*)d_in[1];
    const float* emb  = (const float*)d_in[2];
    const float* Wa   = (const float*)d_in[3];
    const float* ba   = (const float*)d_in[4];
    const float* Wb   = (const float*)d_in[5];
    const float* bb   = (const float*)d_in[6];
    const float* Wlin = (const float*)d_in[7];
    const float* blin = (const float*)d_in[8];
    float* out = (float*)d_out;

    const int* src = ei;
    const int* dst = ei + NE;

    cudaFuncSetAttribute(k_gemm, cudaFuncAttributeMaxDynamicSharedMemorySize, SM_TOTAL);

    // CSR build
    k_zero<<<(NN + 255) / 256, 256>>>();
    k_count<<<(NE + 255) / 256, 256>>>(dst);
    k_scan_block<<<(NN + 1023) / 1024, 1024>>>();
    k_scan_top<<<1, 128>>>();
    k_scan_add<<<(NN + 255) / 256, 256>>>();
    k_scatter<<<(NE + 255) / 256, 256>>>(src, dst);

    // weight transpose/split + embedding gather
    k_wconv<<<NLAYER * 2 * 4, 256>>>(Wa, Wb);
    k_gather<<<(NN * 32 + 255) / 256, 256>>>(x, emb);

    // layers (ping-pong)
    void *pA, *pB, *pW;
    cudaGetSymbolAddress(&pA, g_hA);
    cudaGetSymbolAddress(&pB, g_hB);
    cudaGetSymbolAddress(&pW, g_Wt);
    float* hbuf[2] = {(float*)pA, (float*)pB};
    const unsigned char* Wt = (const unsigned char*)pW;
    int cur = 0;
    const int aggGrid = (NN + 7) / 8;
    for (int l = 0; l < NLAYER; l++) {
        k_agg<<<aggGrid, 256>>>(hbuf[cur]);
        k_gemm<<<NBLK, 512, SM_TOTAL>>>(hbuf[1 - cur],
                                        Wt + (size_t)l * 4 * IMG,
                                        ba + (size_t)l * DD, bb + (size_t)l * DD);
        cur ^= 1;
    }

    // pool + head
    k_pool<<<256, 128>>>(hbuf[cur]);
    k_final<<<1, 128>>>(Wlin, blin, out);
}

// round 16
// speedup vs baseline: 3.1960x; 1.0099x over previous
#include <cuda_runtime.h>
#include <cuda_bf16.h>
#include <cstdint>

#define NN 100000
#define NE 600000
#define DD 128
#define NLAYER 5
#define TILE_M 256
#define NBLK ((NN + TILE_M - 1) / TILE_M)
#define ZROWS (NBLK * TILE_M)           // 100096 rows in z images

#define PITCH 272                       // bytes per 128-bf16 row (256 + 16 pad)
#define IMG   (128 * PITCH)             // 34816 bytes per weight image
#define AIMG  (TILE_M * PITCH)          // 69632 bytes per A image
#define WPAIR (2 * IMG)                 // hi+lo pair = 69632

// SMEM layout (bytes)
#define SM_MBARA  0
#define SM_MBARW0 8
#define SM_MBARW1 16
#define SM_BA   32
#define SM_BB   544
#define SM_A    1088                    // A_hi image (256 rows)
#define SM_AL   (SM_A + AIMG)           // A_lo image
#define SM_W    (SM_AL + AIMG)          // weight pair buffer (hi|lo)
#define SM_TOTAL (SM_W + WPAIR)         // 209984 bytes

// ---------------- scratch ----------------
__device__ __align__(128) float g_hA[NN * DD];
__device__ __align__(128) float g_hB[NN * DD];
__device__ int   g_deg[NN];
__device__ int   g_rowstart[NN + 1];
__device__ int   g_cursor[NN];
__device__ int   g_csr[NE];
__device__ int   g_bsum[128];
__device__ int   g_boff[128];
__device__ float g_pp[256 * DD];
__device__ __align__(128) unsigned char g_Wt[NLAYER * 4 * IMG];  // [WaH|WaL|WbH|WbL] per layer
__device__ __align__(128) unsigned char g_zH[ZROWS * PITCH];     // z hi image
__device__ __align__(128) unsigned char g_zL[ZROWS * PITCH];     // z lo image

// ---------------- helpers ----------------
__device__ __forceinline__ uint32_t smem_u32(const void* p) {
    uint32_t a;
    asm("{ .reg .u64 t; cvta.to.shared.u64 t, %1; cvt.u32.u64 %0, t; }" : "=r"(a) : "l"(p));
    return a;
}
#define MBAR_INIT(a, c) asm volatile("mbarrier.init.shared.b64 [%0], %1;" :: "r"(a), "r"(c) : "memory")
#define MBAR_EXPECT(a, b) asm volatile("mbarrier.arrive.expect_tx.shared.b64 _, [%0], %1;" :: "r"(a), "r"(b) : "memory")
#define MBAR_WAIT(a, ph) do { \
    uint32_t _m = (a), _p = (ph), _d; \
    asm volatile("{\n\t.reg .pred p;\n\tmbarrier.try_wait.parity.acquire.cta.shared::cta.b64 p, [%1], %2;\n\tselp.b32 %0, 1, 0, p;\n\t}" \
        : "=r"(_d) : "r"(_m), "r"(_p) : "memory"); \
    if (!_d) { \
        asm volatile("{\n\t.reg .pred P1;\n\tWL_%=:\n\tmbarrier.try_wait.parity.acquire.cta.shared::cta.b64 P1, [%0], %1, 0x989680;\n\t@P1 bra.uni WD_%=;\n\tbra.uni WL_%=;\n\tWD_%=:\n\t}" \
            :: "r"(_m), "r"(_p) : "memory"); \
    } } while (0)

__device__ __forceinline__ void bulk_g2s(uint32_t dst, const void* src, uint32_t bytes, uint32_t mbar) {
    asm volatile("cp.async.bulk.shared::cta.global.mbarrier::complete_tx::bytes [%0], [%1], %2, [%3];"
        :: "r"(dst), "l"(src), "r"(bytes), "r"(mbar) : "memory");
}

__device__ __forceinline__ void ldsm4(uint32_t* r, uint32_t addr) {
    asm volatile("ldmatrix.sync.aligned.m8n8.x4.shared.b16 {%0,%1,%2,%3}, [%4];"
        : "=r"(r[0]), "=r"(r[1]), "=r"(r[2]), "=r"(r[3]) : "r"(addr));
}
__device__ __forceinline__ void mma16816(float* c, const uint32_t* a, const uint32_t* b) {
    asm volatile("mma.sync.aligned.m16n8k16.row.col.f32.bf16.bf16.f32 "
        "{%0,%1,%2,%3}, {%4,%5,%6,%7}, {%8,%9}, {%0,%1,%2,%3};"
        : "+f"(c[0]), "+f"(c[1]), "+f"(c[2]), "+f"(c[3])
        : "r"(a[0]), "r"(a[1]), "r"(a[2]), "r"(a[3]), "r"(b[0]), "r"(b[1]));
}
// pack two floats as bf16x2: low 16 bits = first arg
__device__ __forceinline__ uint32_t pack_bf2(float lo_e, float hi_e) {
    uint32_t r;
    asm("cvt.rn.bf16x2.f32 %0, %1, %2;" : "=r"(r) : "f"(hi_e), "f"(lo_e));
    return r;
}

// ---------------- CSR build ----------------
__global__ void k_zero() {
    int i = blockIdx.x * blockDim.x + threadIdx.x;
    if (i < NN) g_deg[i] = 0;
}
__global__ void k_count(const int* __restrict__ dst) {
    int e = blockIdx.x * blockDim.x + threadIdx.x;
    if (e < NE) atomicAdd(&g_deg[dst[e]], 1);
}
__global__ void k_scan_block() {
    __shared__ int s[1024];
    int tid = threadIdx.x;
    int i = blockIdx.x * 1024 + tid;
    int v = (i < NN) ? g_deg[i] : 0;
    s[tid] = v;
    __syncthreads();
    for (int off = 1; off < 1024; off <<= 1) {
        int t = (tid >= off) ? s[tid - off] : 0;
        __syncthreads();
        s[tid] += t;
        __syncthreads();
    }
    if (i < NN) g_rowstart[i] = s[tid] - v;
    if (tid == 1023) g_bsum[blockIdx.x] = s[1023];
}
__global__ void k_scan_top() {
    __shared__ int s[128];
    int tid = threadIdx.x;
    int v = (tid < (NN + 1023) / 1024) ? g_bsum[tid] : 0;
    s[tid] = v;
    __syncthreads();
    for (int off = 1; off < 128; off <<= 1) {
        int t = (tid >= off) ? s[tid - off] : 0;
        __syncthreads();
        s[tid] += t;
        __syncthreads();
    }
    g_boff[tid] = s[tid] - v;
}
__global__ void k_scan_add() {
    int i = blockIdx.x * blockDim.x + threadIdx.x;
    if (i < NN) {
        int r = g_rowstart[i] + g_boff[i >> 10];
        g_rowstart[i] = r;
        g_cursor[i] = r;
    }
    if (i == 0) g_rowstart[NN] = NE;
}
__global__ void k_scatter(const int* __restrict__ src, const int* __restrict__ dst) {
    int e = blockIdx.x * blockDim.x + threadIdx.x;
    if (e < NE) {
        int p = atomicAdd(&g_cursor[dst[e]], 1);
        g_csr[p] = src[e];
    }
}

// ---------------- embedding gather ----------------
__global__ void k_gather(const int* __restrict__ x, const float* __restrict__ emb) {
    int idx = blockIdx.x * blockDim.x + threadIdx.x;
    if (idx < NN * 32) {
        int node = idx >> 5, q = idx & 31;
        ((float4*)g_hA)[(size_t)node * 32 + q] = ((const float4*)emb)[(size_t)x[node] * 32 + q];
    }
}

// ---------------- weight transpose + bf16 hi/lo split ----------------
__global__ void k_wconv(const float* __restrict__ Wa, const float* __restrict__ Wb) {
    __shared__ float tile[128 * 33];     // [k][n_local]
    int b = blockIdx.x;
    int l = b >> 3;
    int m = (b >> 2) & 1;
    int q = b & 3;
    int n0 = q * 32;
    const float* W = (m == 0 ? Wa : Wb) + (size_t)l * 16384;
    int tid = threadIdx.x;
    for (int idx = tid; idx < 128 * 32; idx += 256) {
        int k = idx >> 5, nn = idx & 31;
        tile[k * 33 + nn] = W[k * 128 + n0 + nn];
    }
    __syncthreads();
    int wid = tid >> 5, lane = tid & 31;
    unsigned char* hiImg = g_Wt + ((size_t)l * 4 + (size_t)m * 2) * IMG;
    unsigned char* loImg = hiImg + IMG;
    for (int i = 0; i < 4; i++) {
        int nl = wid * 4 + i;
        int n = n0 + nl;
        int k0 = lane * 4;
        float w0 = tile[(k0 + 0) * 33 + nl];
        float w1 = tile[(k0 + 1) * 33 + nl];
        float w2 = tile[(k0 + 2) * 33 + nl];
        float w3 = tile[(k0 + 3) * 33 + nl];
        float h0 = __bfloat162float(__float2bfloat16_rn(w0));
        float h1 = __bfloat162float(__float2bfloat16_rn(w1));
        float h2 = __bfloat162float(__float2bfloat16_rn(w2));
        float h3 = __bfloat162float(__float2bfloat16_rn(w3));
        uint2 hv = make_uint2(pack_bf2(h0, h1), pack_bf2(h2, h3));
        uint2 lv = make_uint2(pack_bf2(w0 - h0, w1 - h1), pack_bf2(w2 - h2, w3 - h3));
        *(uint2*)(hiImg + n * PITCH + lane * 8) = hv;
        *(uint2*)(loImg + n * PITCH + lane * 8) = lv;
    }
}

// ---------------- aggregation: warp-per-node, full occupancy ----------------
__global__ void __launch_bounds__(256) k_agg(const float* __restrict__ h_in) {
    int row = blockIdx.x * 8 + (threadIdx.x >> 5);
    int lane = threadIdx.x & 31;
    if (row >= NN) return;
    float4 acc = ((const float4*)(h_in + (size_t)row * DD))[lane];
    int j = g_rowstart[row], end = g_rowstart[row + 1];
    for (; j + 4 <= end; j += 4) {
        int s0 = g_csr[j], s1 = g_csr[j + 1], s2 = g_csr[j + 2], s3 = g_csr[j + 3];
        float4 v0 = ((const float4*)(h_in + (size_t)s0 * DD))[lane];
        float4 v1 = ((const float4*)(h_in + (size_t)s1 * DD))[lane];
        float4 v2 = ((const float4*)(h_in + (size_t)s2 * DD))[lane];
        float4 v3 = ((const float4*)(h_in + (size_t)s3 * DD))[lane];
        acc.x += (v0.x + v1.x) + (v2.x + v3.x);
        acc.y += (v0.y + v1.y) + (v2.y + v3.y);
        acc.z += (v0.z + v1.z) + (v2.z + v3.z);
        acc.w += (v0.w + v1.w) + (v2.w + v3.w);
    }
    for (; j < end; j++) {
        int s0 = g_csr[j];
        float4 v0 = ((const float4*)(h_in + (size_t)s0 * DD))[lane];
        acc.x += v0.x; acc.y += v0.y; acc.z += v0.z; acc.w += v0.w;
    }
    float hx = __bfloat162float(__float2bfloat16_rn(acc.x));
    float hy = __bfloat162float(__float2bfloat16_rn(acc.y));
    float hz = __bfloat162float(__float2bfloat16_rn(acc.z));
    float hw = __bfloat162float(__float2bfloat16_rn(acc.w));
    uint2 hv = make_uint2(pack_bf2(hx, hy), pack_bf2(hz, hw));
    uint2 lv = make_uint2(pack_bf2(acc.x - hx, acc.y - hy), pack_bf2(acc.z - hz, acc.w - hw));
    *(uint2*)(g_zH + (size_t)row * PITCH + lane * 8) = hv;
    *(uint2*)(g_zL + (size_t)row * PITCH + lane * 8) = lv;
}

// ---------------- GEMM kernel: bulk-load z images + 2x bf16x3 mma.sync ----------------
// B-fragments fetched via ldmatrix.x4 (paired n-columns) to halve LDSM issue count.
__global__ void __launch_bounds__(512, 1) k_gemm(
    float* __restrict__ h_out,
    const unsigned char* __restrict__ Wt,   // [WaH|WaL|WbH|WbL]
    const float* __restrict__ ba, const float* __restrict__ bb)
{
    extern __shared__ char smem[];
    const uint32_t sb = smem_u32(smem);
    float* ba_s = (float*)(smem + SM_BA);
    float* bb_s = (float*)(smem + SM_BB);
    const int tid = threadIdx.x;
    const int wid = tid >> 5;
    const int lane = tid & 31;
    const int base = blockIdx.x * TILE_M;
    const int m0 = wid * 16;

    if (tid == 0) {
        MBAR_INIT(sb + SM_MBARA, 1);
        MBAR_INIT(sb + SM_MBARW0, 1);
        MBAR_INIT(sb + SM_MBARW1, 1);
    }
    if (tid < 128) { ba_s[tid] = ba[tid]; bb_s[tid] = bb[tid]; }
    __syncthreads();
    if (tid == 0) {
        MBAR_EXPECT(sb + SM_MBARA, 2u * AIMG);
        bulk_g2s(sb + SM_A,  g_zH + (size_t)base * PITCH, AIMG, sb + SM_MBARA);
        bulk_g2s(sb + SM_AL, g_zL + (size_t)base * PITCH, AIMG, sb + SM_MBARA);
        MBAR_EXPECT(sb + SM_MBARW0, WPAIR);
        bulk_g2s(sb + SM_W, Wt, WPAIR, sb + SM_MBARW0);   // WaH|WaL
    }
    MBAR_WAIT(sb + SM_MBARA, 0);
    MBAR_WAIT(sb + SM_MBARW0, 0);

    // per-thread ldmatrix addresses
    const uint32_t aBase = sb + SM_A + (uint32_t)(m0 + (lane & 15)) * PITCH + ((lane >> 4) << 4);
    // x4 B-fragment lane offset: groups of 8 lanes -> (n0,k0),(n0,k8),(n8,k0),(n8,k8)
    const uint32_t bLane4 = (uint32_t)((lane & 7) + ((lane >> 4) << 3)) * PITCH
                          + (((lane >> 3) & 1) << 4);
    const int colq = (lane & 3) * 2;
    const int rq = lane >> 2;

    // ================= GEMM1: t = relu(z3 @ Wa3 + ba) =================
    {
        uint32_t aH[8][4], aL[8][4];
        #pragma unroll
        for (int ks = 0; ks < 8; ks++) {
            ldsm4(aH[ks], aBase + ks * 32);
            ldsm4(aL[ks], aBase + AIMG + ks * 32);
        }
        const uint32_t bHB = sb + SM_W;           // WaH
        const uint32_t bLB = sb + SM_W + IMG;     // WaL
        #pragma unroll 1
        for (int p = 0; p < 8; p++) {
            int n0 = p * 16;
            float c0[4] = {0.f, 0.f, 0.f, 0.f};
            float c1[4] = {0.f, 0.f, 0.f, 0.f};
            uint32_t bo = (uint32_t)n0 * PITCH + bLane4;
            #pragma unroll
            for (int ks = 0; ks < 8; ks++) {
                uint32_t bH[4], bL[4];
                ldsm4(bH, bHB + bo + ks * 32);
                ldsm4(bL, bLB + bo + ks * 32);
                mma16816(c0, aH[ks], bH);
                mma16816(c0, aH[ks], bL);
                mma16816(c0, aL[ks], bH);
                mma16816(c1, aH[ks], bH + 2);
                mma16816(c1, aH[ks], bL + 2);
                mma16816(c1, aL[ks], bH + 2);
            }
            // epilogue 1 for both n-columns: bias + relu, split, overwrite A images
            #pragma unroll
            for (int h8 = 0; h8 < 2; h8++) {
                float* c = h8 ? c1 : c0;
                int col = n0 + h8 * 8 + colq;
                float b0 = ba_s[col], b1 = ba_s[col + 1];
                float t00 = fmaxf(c[0] + b0, 0.f), t01 = fmaxf(c[1] + b1, 0.f);
                float t10 = fmaxf(c[2] + b0, 0.f), t11 = fmaxf(c[3] + b1, 0.f);
                float h00 = __bfloat162float(__float2bfloat16_rn(t00));
                float h01 = __bfloat162float(__float2bfloat16_rn(t01));
                float h10 = __bfloat162float(__float2bfloat16_rn(t10));
                float h11 = __bfloat162float(__float2bfloat16_rn(t11));
                uint32_t o0 = (uint32_t)(m0 + rq) * PITCH + (uint32_t)col * 2;
                uint32_t o1 = (uint32_t)(m0 + 8 + rq) * PITCH + (uint32_t)col * 2;
                *(uint32_t*)(smem + SM_A  + o0) = pack_bf2(h00, h01);
                *(uint32_t*)(smem + SM_A  + o1) = pack_bf2(h10, h11);
                *(uint32_t*)(smem + SM_AL + o0) = pack_bf2(t00 - h00, t01 - h01);
                *(uint32_t*)(smem + SM_AL + o1) = pack_bf2(t10 - h10, t11 - h11);
            }
        }
    }
    // all warps must finish reading Wa before Wb overwrites the buffer
    __syncthreads();
    if (tid == 0) {
        MBAR_EXPECT(sb + SM_MBARW1, WPAIR);
        bulk_g2s(sb + SM_W, Wt + WPAIR, WPAIR, sb + SM_MBARW1);   // WbH|WbL
    }
    MBAR_WAIT(sb + SM_MBARW1, 0);

    // ================= GEMM2: h' = relu(t3 @ Wb3 + bb) -> global =================
    {
        uint32_t aH[8][4], aL[8][4];
        #pragma unroll
        for (int ks = 0; ks < 8; ks++) {
            ldsm4(aH[ks], aBase + ks * 32);
            ldsm4(aL[ks], aBase + AIMG + ks * 32);
        }
        const uint32_t bHB = sb + SM_W;           // WbH
        const uint32_t bLB = sb + SM_W + IMG;     // WbL
        int gr0 = base + m0 + rq;
        int gr1 = gr0 + 8;
        #pragma unroll 1
        for (int p = 0; p < 8; p++) {
            int n0 = p * 16;
            float c0[4] = {0.f, 0.f, 0.f, 0.f};
            float c1[4] = {0.f, 0.f, 0.f, 0.f};
            uint32_t bo = (uint32_t)n0 * PITCH + bLane4;
            #pragma unroll
            for (int ks = 0; ks < 8; ks++) {
                uint32_t bH[4], bL[4];
                ldsm4(bH, bHB + bo + ks * 32);
                ldsm4(bL, bLB + bo + ks * 32);
                mma16816(c0, aH[ks], bH);
                mma16816(c0, aH[ks], bL);
                mma16816(c0, aL[ks], bH);
                mma16816(c1, aH[ks], bH + 2);
                mma16816(c1, aH[ks], bL + 2);
                mma16816(c1, aL[ks], bH + 2);
            }
            #pragma unroll
            for (int h8 = 0; h8 < 2; h8++) {
                float* c = h8 ? c1 : c0;
                int col = n0 + h8 * 8 + colq;
                float b0 = bb_s[col], b1 = bb_s[col + 1];
                if (gr0 < NN) {
                    float2 o;
                    o.x = fmaxf(c[0] + b0, 0.f);
                    o.y = fmaxf(c[1] + b1, 0.f);
                    *(float2*)(h_out + (size_t)gr0 * DD + col) = o;
                }
                if (gr1 < NN) {
                    float2 o;
                    o.x = fmaxf(c[2] + b0, 0.f);
                    o.y = fmaxf(c[3] + b1, 0.f);
                    *(float2*)(h_out + (size_t)gr1 * DD + col) = o;
                }
            }
        }
    }
}

// ---------------- pooling + head ----------------
__global__ void k_pool(const float* __restrict__ h) {
    int c = threadIdx.x;
    float acc = 0.f;
    #pragma unroll 8
    for (int i = blockIdx.x; i < NN; i += gridDim.x)
        acc += h[(size_t)i * DD + c];
    g_pp[blockIdx.x * DD + c] = acc;
}
__global__ void k_final(const float* __restrict__ Wlin, const float* __restrict__ blin,
                        float* __restrict__ out) {
    __shared__ float p[DD];
    int c = threadIdx.x;
    float acc = 0.f;
    for (int b = 0; b < 256; b++) acc += g_pp[b * DD + c];
    p[c] = acc;
    __syncthreads();
    float o = blin[c];
    #pragma unroll 8
    for (int k = 0; k < DD; k++) o += p[k] * Wlin[k * DD + c];
    out[c] = o;
}

// ---------------- launch ----------------
extern "C" void kernel_launch(void* const* d_in, const int* in_sizes, int n_in,
                              void* d_out, int out_size) {
    const int*   x    = (const int*)d_in[0];
    const int*   ei   = (const int*)d_in[1];
    const float* emb  = (const float*)d_in[2];
    const float* Wa   = (const float*)d_in[3];
    const float* ba   = (const float*)d_in[4];
    const float* Wb   = (const float*)d_in[5];
    const float* bb   = (const float*)d_in[6];
    const float* Wlin = (const float*)d_in[7];
    const float* blin = (const float*)d_in[8];
    float* out = (float*)d_out;

    const int* src = ei;
    const int* dst = ei + NE;

    cudaFuncSetAttribute(k_gemm, cudaFuncAttributeMaxDynamicSharedMemorySize, SM_TOTAL);

    // CSR build
    k_zero<<<(NN + 255) / 256, 256>>>();
    k_count<<<(NE + 255) / 256, 256>>>(dst);
    k_scan_block<<<(NN + 1023) / 1024, 1024>>>();
    k_scan_top<<<1, 128>>>();
    k_scan_add<<<(NN + 255) / 256, 256>>>();
    k_scatter<<<(NE + 255) / 256, 256>>>(src, dst);

    // weight transpose/split + embedding gather
    k_wconv<<<NLAYER * 2 * 4, 256>>>(Wa, Wb);
    k_gather<<<(NN * 32 + 255) / 256, 256>>>(x, emb);

    // layers (ping-pong)
    void *pA, *pB, *pW;
    cudaGetSymbolAddress(&pA, g_hA);
    cudaGetSymbolAddress(&pB, g_hB);
    cudaGetSymbolAddress(&pW, g_Wt);
    float* hbuf[2] = {(float*)pA, (float*)pB};
    const unsigned char* Wt = (const unsigned char*)pW;
    int cur = 0;
    const int aggGrid = (NN + 7) / 8;
    for (int l = 0; l < NLAYER; l++) {
        k_agg<<<aggGrid, 256>>>(hbuf[cur]);
        k_gemm<<<NBLK, 512, SM_TOTAL>>>(hbuf[1 - cur],
                                        Wt + (size_t)l * 4 * IMG,
                                        ba + (size_t)l * DD, bb + (size_t)l * DD);
        cur ^= 1;
    }

    // pool + head
    k_pool<<<256, 128>>>(hbuf[cur]);
    k_final<<<1, 128>>>(Wlin, blin, out);
}